// round 14
// baseline (speedup 1.0000x reference)
#include <cuda_runtime.h>
#include <math.h>

// ---------------------------------------------------------------------------
// PathGuidedAggregator: S=8192 x P=16 x K=16, D=128, H=64
// Round 11: R9 (champion, 137.7us) + dynamic node scheduling via global
// atomic counter (work-stealing). Per-node gather cost varies ~30% (binomial
// valid counts); static 18-node slates leave a multi-sigma straggler tail.
// Atomic fetch issued before gather (latency hidden), published via smem slot
// (write->read spans S1; read->next-write spans S2+S3: race-free).
// Phase B frozen at R3 shape (R4/R6/R7/R10 retiles all lost).
// ---------------------------------------------------------------------------

#define DD 128
#define PP 16
#define KK 16
#define HH 64
#define GRID 456                 // 152 SMs x 3 blocks/SM, exactly co-resident
#define AGG_STRIDE 132           // floats per sAgg row
#define PART_PSTRIDE 33          // ull per path row in sPart
#define PART_DQ (16 * PART_PSTRIDE)  // 528 ull per d-quarter

__device__ int g_zero_done = 0;     // blocks that finished zeroing
__device__ int g_exit_cnt  = 0;     // blocks that finished the kernel
__device__ int g_node_ctr  = GRID;  // next unassigned node (nodes 0..GRID-1 static)

// ---- packed f32x2 helpers (sm_100+) ---------------------------------------
__device__ __forceinline__ unsigned long long pack2(float x, float y) {
    unsigned long long r;
    asm("mov.b64 %0, {%1, %2};" : "=l"(r) : "f"(x), "f"(y));
    return r;
}
__device__ __forceinline__ float2 unpack2(unsigned long long v) {
    float2 r;
    asm("mov.b64 {%0, %1}, %2;" : "=f"(r.x), "=f"(r.y) : "l"(v));
    return r;
}
__device__ __forceinline__ void fma2(unsigned long long& acc,
                                     unsigned long long a,
                                     unsigned long long b) {
    asm("fma.rn.f32x2 %0, %1, %2, %0;" : "+l"(acc) : "l"(a), "l"(b));
}

// Dynamic SMEM layout (float index):
//   sW1    [0     .. 8192)    32 KB  W1[d][j] row-major
//   sAgg0  [8192  .. 10304)   16 x 132
//   sAgg1  [10304 .. 12416)   16 x 132
//   sPart  [12416 .. 16640)   4 dq x 528 ull (16.9 KB)
//   sWgt   [16640 .. 16672)   2 x 16
//   sVal   [16672 .. 16704)   2 x 16 (int)
//   sSch   [16704 .. 16712)   next-node slot (int) + pad
static const int SMEM_FLOATS = 16712;   // 66848 B

__global__ void __launch_bounds__(512, 3)
pga_kernel(const float* __restrict__ E, const float* __restrict__ W1,
           const float* __restrict__ b1, const float* __restrict__ W2,
           const float* __restrict__ b2, const int* __restrict__ sids,
           const int* __restrict__ eids, const void* __restrict__ maskp,
           float* __restrict__ out, int S, int out_n) {
    extern __shared__ float smem[];
    float* sW1  = smem;
    unsigned long long* sPart = (unsigned long long*)(smem + 12416);
    int* sSch = (int*)(smem + 16704);

    const int t = threadIdx.x;
    const int lane = t & 31;
    const int warp = t >> 5;
    const int grid = gridDim.x;

    // ---- Zero phase: grid-stride float4 zero of the output ---------------
    {
        float4 z = make_float4(0.f, 0.f, 0.f, 0.f);
        const int n4 = out_n >> 2;
        for (int i = blockIdx.x * 512 + t; i < n4; i += grid * 512)
            ((float4*)out)[i] = z;
        for (int i = (n4 << 2) + blockIdx.x * 512 + t; i < out_n; i += grid * 512)
            out[i] = 0.f;
        __syncthreads();
        if (t == 0) {
            __threadfence();
            atomicAdd(&g_zero_done, 1);
        }
    }

    // ---- Inline mask dtype detection (all blocks agree) -------------------
    int mode;
    {
        const unsigned* mw = (const unsigned*)maskp;
        unsigned v0 = __ldg(mw + t), v1 = __ldg(mw + 512 + t);
        int gt1 = ((v0 > 1u) && (v0 != 0x3F800000u)) ||
                  ((v1 > 1u) && (v1 != 0x3F800000u));
        int one = (v0 == 0x3F800000u) || (v1 == 0x3F800000u);
        int any_gt1 = __syncthreads_or(gt1);
        int any_one = __syncthreads_or(one);
        mode = any_gt1 ? 0 : (any_one ? 2 : 1);
    }

    // W1 -> smem (vectorized)
    {
        const float4* w4 = (const float4*)W1;
        #pragma unroll
        for (int i = t; i < DD * HH / 4; i += 512)
            ((float4*)sW1)[i] = __ldg(w4 + i);
    }
    // Phase C per-thread constants (indexed by lane only)
    const float rb1x = __ldg(b1 + 2 * lane);
    const float rb1y = __ldg(b1 + 2 * lane + 1);
    const float rw2x = __ldg(W2 + 2 * lane);
    const float rw2y = __ldg(W2 + 2 * lane + 1);
    const float bias2 = __ldg(b2);
    __syncthreads();

    // Phase B thread decomposition (R3): t = dq*128 + jgrp*8 + pgrp
    const int dq   = t >> 7;        // 0..3  -> d in [dq*32, dq*32+32)
    const int jgrp = (t >> 3) & 15; // j = jgrp*4 .. +3
    const int pgrp = t & 7;         // paths pgrp and pgrp+8

    bool first = true;
    int buf = 0;
    int sCur = blockIdx.x;
    while (sCur < S) {
        float* sAgg = smem + 8192 + buf * (PP * AGG_STRIDE);
        float* sWgt = smem + 16640 + buf * PP;
        int*   sVal = (int*)(smem + 16672) + buf * PP;

        // fetch next node id (latency hidden under the gather below)
        int v_fetch = 0;
        if (t == 0) v_fetch = atomicAdd(&g_node_ctr, 1);

        // ---------------- Phase A: gather (warp p <-> path p) --------------
        {
            const int p = warp;
            const int base = (sCur * PP + p) * KK;
            const int4* ip = (const int4*)(eids + base);

            unsigned mb = 0;
            if (mode == 0) {
                uint4 mv = __ldg((const uint4*)((const unsigned char*)maskp + base));
                unsigned wds[4] = {mv.x, mv.y, mv.z, mv.w};
                #pragma unroll
                for (int q = 0; q < 4; q++)
                    #pragma unroll
                    for (int b = 0; b < 4; b++)
                        mb |= (((wds[q] >> (8 * b)) & 0xFFu) ? 1u : 0u) << (q * 4 + b);
            } else if (mode == 1) {
                const int4* m4 = (const int4*)((const int*)maskp + base);
                #pragma unroll
                for (int q = 0; q < 4; q++) {
                    int4 mv = __ldg(m4 + q);
                    mb |= (mv.x ? 1u : 0u) << (q * 4 + 0);
                    mb |= (mv.y ? 1u : 0u) << (q * 4 + 1);
                    mb |= (mv.z ? 1u : 0u) << (q * 4 + 2);
                    mb |= (mv.w ? 1u : 0u) << (q * 4 + 3);
                }
            } else {
                const float4* m4 = (const float4*)((const float*)maskp + base);
                #pragma unroll
                for (int q = 0; q < 4; q++) {
                    float4 mv = __ldg(m4 + q);
                    mb |= (mv.x != 0.f ? 1u : 0u) << (q * 4 + 0);
                    mb |= (mv.y != 0.f ? 1u : 0u) << (q * 4 + 1);
                    mb |= (mv.z != 0.f ? 1u : 0u) << (q * 4 + 2);
                    mb |= (mv.w != 0.f ? 1u : 0u) << (q * 4 + 3);
                }
            }
            const int cnt = __popc(mb);

            const float4* E4 = (const float4*)E;
            float4 acc = make_float4(0.f, 0.f, 0.f, 0.f);
            #pragma unroll
            for (int h = 0; h < 2; h++) {
                int4 ia = __ldg(ip + 2 * h);
                int4 ib = __ldg(ip + 2 * h + 1);
                const int ids8[8] = {ia.x, ia.y, ia.z, ia.w, ib.x, ib.y, ib.z, ib.w};
                #pragma unroll
                for (int k = 0; k < 8; k++) {
                    if (mb & (1u << (8 * h + k))) {
                        float4 v = __ldg(E4 + ids8[k] * (DD / 4) + lane);
                        acc.x += v.x; acc.y += v.y; acc.z += v.z; acc.w += v.w;
                    }
                }
            }
            const float inv = 1.f / (float)(cnt > 0 ? cnt : 1);
            float4 a = make_float4(acc.x * inv, acc.y * inv, acc.z * inv, acc.w * inv);
            ((float4*)(sAgg + p * AGG_STRIDE))[lane] = a;
            if (lane == 0) sVal[p] = (cnt > 0);
        }
        if (t == 0) sSch[0] = v_fetch;   // publish next node before S1
        __syncthreads();   // S1: sAgg(buf) + sSch ready
        const int sNxt = sSch[0];

        // -------- Phase B: tiled split-K GEMM h[p][j] partials (R3) ---------
        {
            // prefetch next node's id + mask lines (lane 0 per warp/path)
            if (lane == 0 && sNxt < S) {
                const int nb = (sNxt * PP + warp) * KK;
                asm volatile("prefetch.global.L1 [%0];" :: "l"(eids + nb));
                const char* mpc = (const char*)maskp +
                                  ((mode == 0) ? (size_t)nb : (size_t)nb * 4);
                asm volatile("prefetch.global.L1 [%0];" :: "l"(mpc));
            }

            const float* a0p = sAgg + pgrp * AGG_STRIDE + dq * 32;
            const float* a1p = a0p + 8 * AGG_STRIDE;
            const float* wp  = sW1 + (dq * 32) * HH + jgrp * 4;
            unsigned long long acc00 = 0ull, acc01 = 0ull;
            unsigned long long acc10 = 0ull, acc11 = 0ull;
            #pragma unroll
            for (int step = 0; step < 8; step++) {
                float4 a0 = *(const float4*)(a0p + step * 4);
                float4 a1 = *(const float4*)(a1p + step * 4);
                float av0[4] = {a0.x, a0.y, a0.z, a0.w};
                float av1[4] = {a1.x, a1.y, a1.z, a1.w};
                #pragma unroll
                for (int r = 0; r < 4; r++) {
                    ulonglong2 w = *(const ulonglong2*)(wp + (step * 4 + r) * HH);
                    unsigned long long aa0 = pack2(av0[r], av0[r]);
                    unsigned long long aa1 = pack2(av1[r], av1[r]);
                    fma2(acc00, aa0, w.x); fma2(acc01, aa0, w.y);
                    fma2(acc10, aa1, w.x); fma2(acc11, aa1, w.y);
                }
            }
            unsigned long long* pd = sPart + dq * PART_DQ;
            pd[pgrp       * PART_PSTRIDE + jgrp * 2 + 0] = acc00;
            pd[pgrp       * PART_PSTRIDE + jgrp * 2 + 1] = acc01;
            pd[(pgrp + 8) * PART_PSTRIDE + jgrp * 2 + 0] = acc10;
            pd[(pgrp + 8) * PART_PSTRIDE + jgrp * 2 + 1] = acc11;
        }
        __syncthreads();   // S2: sPart ready

        // ------- Phase C: reduce split-K, bias+relu, dot W2, sigmoid -------
        {
            const int p = warp;
            float hx = 0.f, hy = 0.f;
            #pragma unroll
            for (int dqq = 0; dqq < 4; dqq++) {
                float2 v = unpack2(sPart[dqq * PART_DQ + p * PART_PSTRIDE + lane]);
                hx += v.x; hy += v.y;
            }
            float h0 = fmaxf(hx + rb1x, 0.f);
            float h1 = fmaxf(hy + rb1y, 0.f);
            float hw = h0 * rw2x + h1 * rw2y;
            #pragma unroll
            for (int o = 16; o; o >>= 1) hw += __shfl_xor_sync(0xffffffffu, hw, o);
            if (lane == 0) {
                float x = hw + bias2;
                float w = 1.f / (1.f + __expf(-x));
                sWgt[p] = sVal[p] ? w : 0.f;
            }
        }
        __syncthreads();   // S3: sWgt ready

        // ---- soft grid barrier before the FIRST output write only --------
        if (first) {
            if (t == 0) {
                while (atomicAdd(&g_zero_done, 0) < grid) { }
            }
            __syncthreads();
            first = false;
        }

        // -------- Phase D: weighted mean + scatter (overlaps next gather) ---
        if (t < DD) {
            float o = 0.f;
            int nv = 0;
            #pragma unroll
            for (int p = 0; p < PP; p++) {
                o += sWgt[p] * sAgg[p * AGG_STRIDE + t];
                nv += sVal[p];
            }
            out[__ldg(sids + sCur) * DD + t] = o / (float)(nv > 0 ? nv : 1);
        }
        // no end-of-node sync (double-buffered; sPart fenced by S1+S2 next).

        sCur = sNxt;
        buf ^= 1;
    }

    // ---- reset counters for deterministic graph replay --------------------
    __syncthreads();
    if (t == 0) {
        __threadfence();
        int d = atomicAdd(&g_exit_cnt, 1);
        if (d == grid - 1) {
            g_zero_done = 0;
            g_exit_cnt  = 0;
            g_node_ctr  = GRID;
        }
    }
}

extern "C" void kernel_launch(void* const* d_in, const int* in_sizes, int n_in,
                              void* d_out, int out_size) {
    const float* E   = (const float*)d_in[0];
    const float* W1  = (const float*)d_in[1];
    const float* b1  = (const float*)d_in[2];
    const float* W2  = (const float*)d_in[3];
    const float* b2  = (const float*)d_in[4];
    const int*   sid = (const int*)d_in[5];
    const int*   eid = (const int*)d_in[6];
    const void*  msk = d_in[7];
    float* out = (float*)d_out;

    const int S = in_sizes[5];

    static const int SMEM_BYTES = SMEM_FLOATS * 4; // 66848 B
    cudaFuncSetAttribute(pga_kernel, cudaFuncAttributeMaxDynamicSharedMemorySize,
                         SMEM_BYTES);

    // GRID=456: 152 SMs x 3 blocks/SM — exactly co-resident (soft barrier +
    // static counter init both rely on this).
    pga_kernel<<<GRID, 512, SMEM_BYTES>>>(E, W1, b1, W2, b2, sid, eid, msk,
                                          out, S, out_size);
}

// round 16
// speedup vs baseline: 1.4916x; 1.4916x over previous
#include <cuda_runtime.h>
#include <math.h>

// ---------------------------------------------------------------------------
// PathGuidedAggregator: S=8192 x P=16 x K=16, D=128, H=64
// Round 12: exact R9 (champion, 137.7us) + asymmetric S3 via named barriers:
// warps 4-15 bar.arrive (non-blocking) and flow into the next node's gather,
// overlapping Phase D (which only warps 0-3 execute). First-iteration zero-
// spin moves inside the D-warp group (bar.sync 2,128). Everything else
// byte-identical to R9. (R11's global-atomic work stealing regressed 74us —
// contended single-address ATOMG on the critical path; never again.)
// ---------------------------------------------------------------------------

#define DD 128
#define PP 16
#define KK 16
#define HH 64
#define AGG_STRIDE 132           // floats per sAgg row
#define PART_PSTRIDE 33          // ull per path row in sPart
#define PART_DQ (16 * PART_PSTRIDE)  // 528 ull per d-quarter

__device__ int g_zero_done = 0;   // blocks that finished zeroing
__device__ int g_exit_cnt  = 0;   // blocks that finished the kernel

// ---- packed f32x2 helpers (sm_100+) ---------------------------------------
__device__ __forceinline__ unsigned long long pack2(float x, float y) {
    unsigned long long r;
    asm("mov.b64 %0, {%1, %2};" : "=l"(r) : "f"(x), "f"(y));
    return r;
}
__device__ __forceinline__ float2 unpack2(unsigned long long v) {
    float2 r;
    asm("mov.b64 {%0, %1}, %2;" : "=f"(r.x), "=f"(r.y) : "l"(v));
    return r;
}
__device__ __forceinline__ void fma2(unsigned long long& acc,
                                     unsigned long long a,
                                     unsigned long long b) {
    asm("fma.rn.f32x2 %0, %1, %2, %0;" : "+l"(acc) : "l"(a), "l"(b));
}

// Dynamic SMEM layout (float index):
//   sW1    [0     .. 8192)    32 KB  W1[d][j] row-major
//   sAgg0  [8192  .. 10304)   16 x 132
//   sAgg1  [10304 .. 12416)   16 x 132
//   sPart  [12416 .. 16640)   4 dq x 528 ull (16.9 KB)
//   sWgt   [16640 .. 16672)   2 x 16
//   sVal   [16672 .. 16704)   2 x 16 (int)
static const int SMEM_FLOATS = 16704;   // 66816 B

__global__ void __launch_bounds__(512, 3)
pga_kernel(const float* __restrict__ E, const float* __restrict__ W1,
           const float* __restrict__ b1, const float* __restrict__ W2,
           const float* __restrict__ b2, const int* __restrict__ sids,
           const int* __restrict__ eids, const void* __restrict__ maskp,
           float* __restrict__ out, int S, int out_n) {
    extern __shared__ float smem[];
    float* sW1  = smem;
    unsigned long long* sPart = (unsigned long long*)(smem + 12416);

    const int t = threadIdx.x;
    const int lane = t & 31;
    const int warp = t >> 5;
    const int grid = gridDim.x;

    // ---- Zero phase: grid-stride float4 zero of the output ---------------
    {
        float4 z = make_float4(0.f, 0.f, 0.f, 0.f);
        const int n4 = out_n >> 2;
        for (int i = blockIdx.x * 512 + t; i < n4; i += grid * 512)
            ((float4*)out)[i] = z;
        for (int i = (n4 << 2) + blockIdx.x * 512 + t; i < out_n; i += grid * 512)
            out[i] = 0.f;
        __syncthreads();
        if (t == 0) {
            __threadfence();
            atomicAdd(&g_zero_done, 1);
        }
    }

    // ---- Inline mask dtype detection (all blocks agree) -------------------
    int mode;
    {
        const unsigned* mw = (const unsigned*)maskp;
        unsigned v0 = __ldg(mw + t), v1 = __ldg(mw + 512 + t);
        int gt1 = ((v0 > 1u) && (v0 != 0x3F800000u)) ||
                  ((v1 > 1u) && (v1 != 0x3F800000u));
        int one = (v0 == 0x3F800000u) || (v1 == 0x3F800000u);
        int any_gt1 = __syncthreads_or(gt1);
        int any_one = __syncthreads_or(one);
        mode = any_gt1 ? 0 : (any_one ? 2 : 1);
    }

    // W1 -> smem (vectorized)
    {
        const float4* w4 = (const float4*)W1;
        #pragma unroll
        for (int i = t; i < DD * HH / 4; i += 512)
            ((float4*)sW1)[i] = __ldg(w4 + i);
    }
    // Phase C per-thread constants (indexed by lane only)
    const float rb1x = __ldg(b1 + 2 * lane);
    const float rb1y = __ldg(b1 + 2 * lane + 1);
    const float rw2x = __ldg(W2 + 2 * lane);
    const float rw2y = __ldg(W2 + 2 * lane + 1);
    const float bias2 = __ldg(b2);
    __syncthreads();

    // Phase B thread decomposition (R3): t = dq*128 + jgrp*8 + pgrp
    const int dq   = t >> 7;        // 0..3  -> d in [dq*32, dq*32+32)
    const int jgrp = (t >> 3) & 15; // j = jgrp*4 .. +3
    const int pgrp = t & 7;         // paths pgrp and pgrp+8

    bool first = true;
    int buf = 0;
    for (int s = blockIdx.x; s < S; s += grid, buf ^= 1) {
        float* sAgg = smem + 8192 + buf * (PP * AGG_STRIDE);
        float* sWgt = smem + 16640 + buf * PP;
        int*   sVal = (int*)(smem + 16672) + buf * PP;

        // ---------------- Phase A: gather (warp p <-> path p) --------------
        {
            const int p = warp;
            const int base = (s * PP + p) * KK;
            const int4* ip = (const int4*)(eids + base);

            if (lane == 0 && s + grid < S) {
                const int nb = ((s + grid) * PP + p) * KK;
                asm volatile("prefetch.global.L1 [%0];" :: "l"(eids + nb));
                const char* mpc = (const char*)maskp +
                                  ((mode == 0) ? (size_t)nb : (size_t)nb * 4);
                asm volatile("prefetch.global.L1 [%0];" :: "l"(mpc));
            }

            unsigned mb = 0;
            if (mode == 0) {
                uint4 mv = __ldg((const uint4*)((const unsigned char*)maskp + base));
                unsigned wds[4] = {mv.x, mv.y, mv.z, mv.w};
                #pragma unroll
                for (int q = 0; q < 4; q++)
                    #pragma unroll
                    for (int b = 0; b < 4; b++)
                        mb |= (((wds[q] >> (8 * b)) & 0xFFu) ? 1u : 0u) << (q * 4 + b);
            } else if (mode == 1) {
                const int4* m4 = (const int4*)((const int*)maskp + base);
                #pragma unroll
                for (int q = 0; q < 4; q++) {
                    int4 mv = __ldg(m4 + q);
                    mb |= (mv.x ? 1u : 0u) << (q * 4 + 0);
                    mb |= (mv.y ? 1u : 0u) << (q * 4 + 1);
                    mb |= (mv.z ? 1u : 0u) << (q * 4 + 2);
                    mb |= (mv.w ? 1u : 0u) << (q * 4 + 3);
                }
            } else {
                const float4* m4 = (const float4*)((const float*)maskp + base);
                #pragma unroll
                for (int q = 0; q < 4; q++) {
                    float4 mv = __ldg(m4 + q);
                    mb |= (mv.x != 0.f ? 1u : 0u) << (q * 4 + 0);
                    mb |= (mv.y != 0.f ? 1u : 0u) << (q * 4 + 1);
                    mb |= (mv.z != 0.f ? 1u : 0u) << (q * 4 + 2);
                    mb |= (mv.w != 0.f ? 1u : 0u) << (q * 4 + 3);
                }
            }
            const int cnt = __popc(mb);

            const float4* E4 = (const float4*)E;
            float4 acc = make_float4(0.f, 0.f, 0.f, 0.f);
            #pragma unroll
            for (int h = 0; h < 2; h++) {
                int4 ia = __ldg(ip + 2 * h);
                int4 ib = __ldg(ip + 2 * h + 1);
                const int ids8[8] = {ia.x, ia.y, ia.z, ia.w, ib.x, ib.y, ib.z, ib.w};
                #pragma unroll
                for (int k = 0; k < 8; k++) {
                    if (mb & (1u << (8 * h + k))) {
                        float4 v = __ldg(E4 + ids8[k] * (DD / 4) + lane);
                        acc.x += v.x; acc.y += v.y; acc.z += v.z; acc.w += v.w;
                    }
                }
            }
            const float inv = 1.f / (float)(cnt > 0 ? cnt : 1);
            float4 a = make_float4(acc.x * inv, acc.y * inv, acc.z * inv, acc.w * inv);
            ((float4*)(sAgg + p * AGG_STRIDE))[lane] = a;
            if (lane == 0) sVal[p] = (cnt > 0);
        }
        __syncthreads();   // S1: sAgg(buf) ready

        // -------- Phase B: tiled split-K GEMM h[p][j] partials (R3) ---------
        {
            const float* a0p = sAgg + pgrp * AGG_STRIDE + dq * 32;
            const float* a1p = a0p + 8 * AGG_STRIDE;
            const float* wp  = sW1 + (dq * 32) * HH + jgrp * 4;
            unsigned long long acc00 = 0ull, acc01 = 0ull;
            unsigned long long acc10 = 0ull, acc11 = 0ull;
            #pragma unroll
            for (int step = 0; step < 8; step++) {
                float4 a0 = *(const float4*)(a0p + step * 4);
                float4 a1 = *(const float4*)(a1p + step * 4);
                float av0[4] = {a0.x, a0.y, a0.z, a0.w};
                float av1[4] = {a1.x, a1.y, a1.z, a1.w};
                #pragma unroll
                for (int r = 0; r < 4; r++) {
                    ulonglong2 w = *(const ulonglong2*)(wp + (step * 4 + r) * HH);
                    unsigned long long aa0 = pack2(av0[r], av0[r]);
                    unsigned long long aa1 = pack2(av1[r], av1[r]);
                    fma2(acc00, aa0, w.x); fma2(acc01, aa0, w.y);
                    fma2(acc10, aa1, w.x); fma2(acc11, aa1, w.y);
                }
            }
            unsigned long long* pd = sPart + dq * PART_DQ;
            pd[pgrp       * PART_PSTRIDE + jgrp * 2 + 0] = acc00;
            pd[pgrp       * PART_PSTRIDE + jgrp * 2 + 1] = acc01;
            pd[(pgrp + 8) * PART_PSTRIDE + jgrp * 2 + 0] = acc10;
            pd[(pgrp + 8) * PART_PSTRIDE + jgrp * 2 + 1] = acc11;
        }
        __syncthreads();   // S2: sPart ready

        // ------- Phase C: reduce split-K, bias+relu, dot W2, sigmoid -------
        {
            const int p = warp;
            float hx = 0.f, hy = 0.f;
            #pragma unroll
            for (int dqq = 0; dqq < 4; dqq++) {
                float2 v = unpack2(sPart[dqq * PART_DQ + p * PART_PSTRIDE + lane]);
                hx += v.x; hy += v.y;
            }
            float h0 = fmaxf(hx + rb1x, 0.f);
            float h1 = fmaxf(hy + rb1y, 0.f);
            float hw = h0 * rw2x + h1 * rw2y;
            #pragma unroll
            for (int o = 16; o; o >>= 1) hw += __shfl_xor_sync(0xffffffffu, hw, o);
            if (lane == 0) {
                float x = hw + bias2;
                float w = 1.f / (1.f + __expf(-x));
                sWgt[p] = sVal[p] ? w : 0.f;
            }
        }

        // ---- S3 split: producers arrive (non-blocking), D-warps sync ------
        if (warp >= 4) {
            asm volatile("bar.arrive 1, 512;" ::: "memory");
            // warps 4-15 flow straight into the next node's Phase A:
            // they write sAgg(buf^1)/sVal(buf^1) (disjoint from what D reads),
            // and sPart(next) writes are fenced behind S1(next)+S2(next).
        } else {
            asm volatile("bar.sync 1, 512;" ::: "memory");   // sWgt ready

            // soft grid barrier before the FIRST output write only
            if (first) {
                if (t == 0) {
                    while (atomicAdd(&g_zero_done, 0) < grid) { }
                }
                asm volatile("bar.sync 2, 128;" ::: "memory");
            }

            // ------ Phase D: weighted mean + scatter (warps 0-3 only) ------
            if (t < DD) {
                float o = 0.f;
                int nv = 0;
                #pragma unroll
                for (int p = 0; p < PP; p++) {
                    o += sWgt[p] * sAgg[p * AGG_STRIDE + t];
                    nv += sVal[p];
                }
                out[__ldg(sids + s) * DD + t] = o / (float)(nv > 0 ? nv : 1);
            }
        }
        first = false;
        // no end-of-node sync (double-buffered; sPart fenced by S1+S2 next).
    }

    // ---- reset counters for deterministic graph replay --------------------
    __syncthreads();
    if (t == 0) {
        __threadfence();
        int d = atomicAdd(&g_exit_cnt, 1);
        if (d == grid - 1) {
            g_zero_done = 0;
            g_exit_cnt  = 0;
        }
    }
}

extern "C" void kernel_launch(void* const* d_in, const int* in_sizes, int n_in,
                              void* d_out, int out_size) {
    const float* E   = (const float*)d_in[0];
    const float* W1  = (const float*)d_in[1];
    const float* b1  = (const float*)d_in[2];
    const float* W2  = (const float*)d_in[3];
    const float* b2  = (const float*)d_in[4];
    const int*   sid = (const int*)d_in[5];
    const int*   eid = (const int*)d_in[6];
    const void*  msk = d_in[7];
    float* out = (float*)d_out;

    const int S = in_sizes[5];

    static const int SMEM_BYTES = SMEM_FLOATS * 4; // 66816 B
    cudaFuncSetAttribute(pga_kernel, cudaFuncAttributeMaxDynamicSharedMemorySize,
                         SMEM_BYTES);

    // 152 SMs x 3 blocks/SM = 456 blocks — exactly co-resident (soft barrier).
    int grid = 456;
    pga_kernel<<<grid, 512, SMEM_BYTES>>>(E, W1, b1, W2, b2, sid, eid, msk,
                                          out, S, out_size);
}

// round 17
// speedup vs baseline: 1.5163x; 1.0165x over previous
#include <cuda_runtime.h>
#include <math.h>

// ---------------------------------------------------------------------------
// PathGuidedAggregator: S=8192 x P=16 x K=16, D=128, H=64
// Round 13: exact R9 (champion, 137.7us; R12's named-barrier split reverted)
// + ld.global.cg for the E-table gather loads: the 1.07GB random-row stream
// has ~0% L1 hit rate, so L1 line allocation + sector fills only add L1
// wavefronts and thrash the carveout. .cg bypasses L1 allocation, keeps L2
// (where the ~21x per-row reuse actually lives).
// ---------------------------------------------------------------------------

#define DD 128
#define PP 16
#define KK 16
#define HH 64
#define AGG_STRIDE 132           // floats per sAgg row
#define PART_PSTRIDE 33          // ull per path row in sPart
#define PART_DQ (16 * PART_PSTRIDE)  // 528 ull per d-quarter

__device__ int g_zero_done = 0;   // blocks that finished zeroing
__device__ int g_exit_cnt  = 0;   // blocks that finished the kernel

// ---- packed f32x2 helpers (sm_100+) ---------------------------------------
__device__ __forceinline__ unsigned long long pack2(float x, float y) {
    unsigned long long r;
    asm("mov.b64 %0, {%1, %2};" : "=l"(r) : "f"(x), "f"(y));
    return r;
}
__device__ __forceinline__ float2 unpack2(unsigned long long v) {
    float2 r;
    asm("mov.b64 {%0, %1}, %2;" : "=f"(r.x), "=f"(r.y) : "l"(v));
    return r;
}
__device__ __forceinline__ void fma2(unsigned long long& acc,
                                     unsigned long long a,
                                     unsigned long long b) {
    asm("fma.rn.f32x2 %0, %1, %2, %0;" : "+l"(acc) : "l"(a), "l"(b));
}
// L2-cached (L1-bypass) 16B load for the streaming E gather
__device__ __forceinline__ float4 ldcg4(const float4* p) {
    float4 v;
    asm volatile("ld.global.cg.v4.f32 {%0, %1, %2, %3}, [%4];"
                 : "=f"(v.x), "=f"(v.y), "=f"(v.z), "=f"(v.w) : "l"(p));
    return v;
}

// Dynamic SMEM layout (float index):
//   sW1    [0     .. 8192)    32 KB  W1[d][j] row-major
//   sAgg0  [8192  .. 10304)   16 x 132
//   sAgg1  [10304 .. 12416)   16 x 132
//   sPart  [12416 .. 16640)   4 dq x 528 ull (16.9 KB)
//   sWgt   [16640 .. 16672)   2 x 16
//   sVal   [16672 .. 16704)   2 x 16 (int)
static const int SMEM_FLOATS = 16704;   // 66816 B

__global__ void __launch_bounds__(512, 3)
pga_kernel(const float* __restrict__ E, const float* __restrict__ W1,
           const float* __restrict__ b1, const float* __restrict__ W2,
           const float* __restrict__ b2, const int* __restrict__ sids,
           const int* __restrict__ eids, const void* __restrict__ maskp,
           float* __restrict__ out, int S, int out_n) {
    extern __shared__ float smem[];
    float* sW1  = smem;
    unsigned long long* sPart = (unsigned long long*)(smem + 12416);

    const int t = threadIdx.x;
    const int lane = t & 31;
    const int warp = t >> 5;
    const int grid = gridDim.x;

    // ---- Zero phase: grid-stride float4 zero of the output ---------------
    {
        float4 z = make_float4(0.f, 0.f, 0.f, 0.f);
        const int n4 = out_n >> 2;
        for (int i = blockIdx.x * 512 + t; i < n4; i += grid * 512)
            ((float4*)out)[i] = z;
        for (int i = (n4 << 2) + blockIdx.x * 512 + t; i < out_n; i += grid * 512)
            out[i] = 0.f;
        __syncthreads();
        if (t == 0) {
            __threadfence();
            atomicAdd(&g_zero_done, 1);
        }
    }

    // ---- Inline mask dtype detection (all blocks agree) -------------------
    int mode;
    {
        const unsigned* mw = (const unsigned*)maskp;
        unsigned v0 = __ldg(mw + t), v1 = __ldg(mw + 512 + t);
        int gt1 = ((v0 > 1u) && (v0 != 0x3F800000u)) ||
                  ((v1 > 1u) && (v1 != 0x3F800000u));
        int one = (v0 == 0x3F800000u) || (v1 == 0x3F800000u);
        int any_gt1 = __syncthreads_or(gt1);
        int any_one = __syncthreads_or(one);
        mode = any_gt1 ? 0 : (any_one ? 2 : 1);
    }

    // W1 -> smem (vectorized)
    {
        const float4* w4 = (const float4*)W1;
        #pragma unroll
        for (int i = t; i < DD * HH / 4; i += 512)
            ((float4*)sW1)[i] = __ldg(w4 + i);
    }
    // Phase C per-thread constants (indexed by lane only)
    const float rb1x = __ldg(b1 + 2 * lane);
    const float rb1y = __ldg(b1 + 2 * lane + 1);
    const float rw2x = __ldg(W2 + 2 * lane);
    const float rw2y = __ldg(W2 + 2 * lane + 1);
    const float bias2 = __ldg(b2);
    __syncthreads();

    // Phase B thread decomposition (R3): t = dq*128 + jgrp*8 + pgrp
    const int dq   = t >> 7;        // 0..3  -> d in [dq*32, dq*32+32)
    const int jgrp = (t >> 3) & 15; // j = jgrp*4 .. +3
    const int pgrp = t & 7;         // paths pgrp and pgrp+8

    bool first = true;
    int buf = 0;
    for (int s = blockIdx.x; s < S; s += grid, buf ^= 1) {
        float* sAgg = smem + 8192 + buf * (PP * AGG_STRIDE);
        float* sWgt = smem + 16640 + buf * PP;
        int*   sVal = (int*)(smem + 16672) + buf * PP;

        // ---------------- Phase A: gather (warp p <-> path p) --------------
        {
            const int p = warp;
            const int base = (s * PP + p) * KK;
            const int4* ip = (const int4*)(eids + base);

            if (lane == 0 && s + grid < S) {
                const int nb = ((s + grid) * PP + p) * KK;
                asm volatile("prefetch.global.L1 [%0];" :: "l"(eids + nb));
                const char* mpc = (const char*)maskp +
                                  ((mode == 0) ? (size_t)nb : (size_t)nb * 4);
                asm volatile("prefetch.global.L1 [%0];" :: "l"(mpc));
            }

            unsigned mb = 0;
            if (mode == 0) {
                uint4 mv = __ldg((const uint4*)((const unsigned char*)maskp + base));
                unsigned wds[4] = {mv.x, mv.y, mv.z, mv.w};
                #pragma unroll
                for (int q = 0; q < 4; q++)
                    #pragma unroll
                    for (int b = 0; b < 4; b++)
                        mb |= (((wds[q] >> (8 * b)) & 0xFFu) ? 1u : 0u) << (q * 4 + b);
            } else if (mode == 1) {
                const int4* m4 = (const int4*)((const int*)maskp + base);
                #pragma unroll
                for (int q = 0; q < 4; q++) {
                    int4 mv = __ldg(m4 + q);
                    mb |= (mv.x ? 1u : 0u) << (q * 4 + 0);
                    mb |= (mv.y ? 1u : 0u) << (q * 4 + 1);
                    mb |= (mv.z ? 1u : 0u) << (q * 4 + 2);
                    mb |= (mv.w ? 1u : 0u) << (q * 4 + 3);
                }
            } else {
                const float4* m4 = (const float4*)((const float*)maskp + base);
                #pragma unroll
                for (int q = 0; q < 4; q++) {
                    float4 mv = __ldg(m4 + q);
                    mb |= (mv.x != 0.f ? 1u : 0u) << (q * 4 + 0);
                    mb |= (mv.y != 0.f ? 1u : 0u) << (q * 4 + 1);
                    mb |= (mv.z != 0.f ? 1u : 0u) << (q * 4 + 2);
                    mb |= (mv.w != 0.f ? 1u : 0u) << (q * 4 + 3);
                }
            }
            const int cnt = __popc(mb);

            const float4* E4 = (const float4*)E;
            float4 acc = make_float4(0.f, 0.f, 0.f, 0.f);
            #pragma unroll
            for (int h = 0; h < 2; h++) {
                int4 ia = __ldg(ip + 2 * h);
                int4 ib = __ldg(ip + 2 * h + 1);
                const int ids8[8] = {ia.x, ia.y, ia.z, ia.w, ib.x, ib.y, ib.z, ib.w};
                #pragma unroll
                for (int k = 0; k < 8; k++) {
                    if (mb & (1u << (8 * h + k))) {
                        float4 v = ldcg4(E4 + ids8[k] * (DD / 4) + lane);
                        acc.x += v.x; acc.y += v.y; acc.z += v.z; acc.w += v.w;
                    }
                }
            }
            const float inv = 1.f / (float)(cnt > 0 ? cnt : 1);
            float4 a = make_float4(acc.x * inv, acc.y * inv, acc.z * inv, acc.w * inv);
            ((float4*)(sAgg + p * AGG_STRIDE))[lane] = a;
            if (lane == 0) sVal[p] = (cnt > 0);
        }
        __syncthreads();   // S1: sAgg(buf) ready

        // -------- Phase B: tiled split-K GEMM h[p][j] partials (R3) ---------
        {
            const float* a0p = sAgg + pgrp * AGG_STRIDE + dq * 32;
            const float* a1p = a0p + 8 * AGG_STRIDE;
            const float* wp  = sW1 + (dq * 32) * HH + jgrp * 4;
            unsigned long long acc00 = 0ull, acc01 = 0ull;
            unsigned long long acc10 = 0ull, acc11 = 0ull;
            #pragma unroll
            for (int step = 0; step < 8; step++) {
                float4 a0 = *(const float4*)(a0p + step * 4);
                float4 a1 = *(const float4*)(a1p + step * 4);
                float av0[4] = {a0.x, a0.y, a0.z, a0.w};
                float av1[4] = {a1.x, a1.y, a1.z, a1.w};
                #pragma unroll
                for (int r = 0; r < 4; r++) {
                    ulonglong2 w = *(const ulonglong2*)(wp + (step * 4 + r) * HH);
                    unsigned long long aa0 = pack2(av0[r], av0[r]);
                    unsigned long long aa1 = pack2(av1[r], av1[r]);
                    fma2(acc00, aa0, w.x); fma2(acc01, aa0, w.y);
                    fma2(acc10, aa1, w.x); fma2(acc11, aa1, w.y);
                }
            }
            unsigned long long* pd = sPart + dq * PART_DQ;
            pd[pgrp       * PART_PSTRIDE + jgrp * 2 + 0] = acc00;
            pd[pgrp       * PART_PSTRIDE + jgrp * 2 + 1] = acc01;
            pd[(pgrp + 8) * PART_PSTRIDE + jgrp * 2 + 0] = acc10;
            pd[(pgrp + 8) * PART_PSTRIDE + jgrp * 2 + 1] = acc11;
        }
        __syncthreads();   // S2: sPart ready

        // ------- Phase C: reduce split-K, bias+relu, dot W2, sigmoid -------
        {
            const int p = warp;
            float hx = 0.f, hy = 0.f;
            #pragma unroll
            for (int dqq = 0; dqq < 4; dqq++) {
                float2 v = unpack2(sPart[dqq * PART_DQ + p * PART_PSTRIDE + lane]);
                hx += v.x; hy += v.y;
            }
            float h0 = fmaxf(hx + rb1x, 0.f);
            float h1 = fmaxf(hy + rb1y, 0.f);
            float hw = h0 * rw2x + h1 * rw2y;
            #pragma unroll
            for (int o = 16; o; o >>= 1) hw += __shfl_xor_sync(0xffffffffu, hw, o);
            if (lane == 0) {
                float x = hw + bias2;
                float w = 1.f / (1.f + __expf(-x));
                sWgt[p] = sVal[p] ? w : 0.f;
            }
        }
        __syncthreads();   // S3: sWgt ready

        // ---- soft grid barrier before the FIRST output write only --------
        if (first) {
            if (t == 0) {
                while (atomicAdd(&g_zero_done, 0) < grid) { }
            }
            __syncthreads();
            first = false;
        }

        // -------- Phase D: weighted mean + scatter (overlaps next gather) ---
        if (t < DD) {
            float o = 0.f;
            int nv = 0;
            #pragma unroll
            for (int p = 0; p < PP; p++) {
                o += sWgt[p] * sAgg[p * AGG_STRIDE + t];
                nv += sVal[p];
            }
            out[__ldg(sids + s) * DD + t] = o / (float)(nv > 0 ? nv : 1);
        }
        // no end-of-node sync (double-buffered; sPart fenced by S1+S2 next).
    }

    // ---- reset counters for deterministic graph replay --------------------
    __syncthreads();
    if (t == 0) {
        __threadfence();
        int d = atomicAdd(&g_exit_cnt, 1);
        if (d == grid - 1) {
            g_zero_done = 0;
            g_exit_cnt  = 0;
        }
    }
}

extern "C" void kernel_launch(void* const* d_in, const int* in_sizes, int n_in,
                              void* d_out, int out_size) {
    const float* E   = (const float*)d_in[0];
    const float* W1  = (const float*)d_in[1];
    const float* b1  = (const float*)d_in[2];
    const float* W2  = (const float*)d_in[3];
    const float* b2  = (const float*)d_in[4];
    const int*   sid = (const int*)d_in[5];
    const int*   eid = (const int*)d_in[6];
    const void*  msk = d_in[7];
    float* out = (float*)d_out;

    const int S = in_sizes[5];

    static const int SMEM_BYTES = SMEM_FLOATS * 4; // 66816 B
    cudaFuncSetAttribute(pga_kernel, cudaFuncAttributeMaxDynamicSharedMemorySize,
                         SMEM_BYTES);

    // 152 SMs x 3 blocks/SM = 456 blocks — exactly co-resident (soft barrier).
    int grid = 456;
    pga_kernel<<<grid, 512, SMEM_BYTES>>>(E, W1, b1, W2, b2, sid, eid, msk,
                                          out, S, out_size);
}